// round 10
// baseline (speedup 1.0000x reference)
#include <cuda_runtime.h>
#include <cuda_bf16.h>
#include <cstdint>

// Problem constants
#define BB 2
#define TT 2048
#define CC 1024
#define HH 16
#define DD 64
#define MM (BB * TT)   // 4096 rows

// ---------------------------------------------------------------------------
// Device scratch (allocation-free per harness rules)
// ---------------------------------------------------------------------------
__device__ __nv_bfloat16 g_qhi[(size_t)BB * HH * TT * DD];
__device__ __nv_bfloat16 g_qlo[(size_t)BB * HH * TT * DD];
__device__ __nv_bfloat16 g_khi[(size_t)BB * HH * TT * DD];
__device__ __nv_bfloat16 g_klo[(size_t)BB * HH * TT * DD];
__device__ __nv_bfloat16 g_vhi[(size_t)BB * HH * TT * DD];
__device__ __nv_bfloat16 g_vlo[(size_t)BB * HH * TT * DD];
__device__ __nv_bfloat16 g_xhi[(size_t)MM * CC];
__device__ __nv_bfloat16 g_xlo[(size_t)MM * CC];
__device__ __nv_bfloat16 g_wahi[(size_t)3 * CC * CC];
__device__ __nv_bfloat16 g_walo[(size_t)3 * CC * CC];
__device__ __nv_bfloat16 g_wphi[(size_t)CC * CC];
__device__ __nv_bfloat16 g_wplo[(size_t)CC * CC];
__device__ __nv_bfloat16 g_ahi[(size_t)MM * CC];
__device__ __nv_bfloat16 g_alo[(size_t)MM * CC];

// ---------------------------------------------------------------------------
// PTX helpers (sm_80+ portable: cp.async / ldmatrix / mma.sync)
// ---------------------------------------------------------------------------
__device__ __forceinline__ uint32_t smem_to_u32(const void* smem_ptr) {
    uint32_t addr;
    asm("{ .reg .u64 tmp; cvta.to.shared.u64 tmp, %1; cvt.u32.u64 %0, tmp; }"
        : "=r"(addr) : "l"(smem_ptr));
    return addr;
}

__device__ __forceinline__ void cpasync16(uint32_t s, const void* g) {
    asm volatile("cp.async.cg.shared.global [%0], [%1], 16;" :: "r"(s), "l"(g) : "memory");
}

#define CP_COMMIT()  asm volatile("cp.async.commit_group;" ::: "memory")
#define CP_WAIT(n)   asm volatile("cp.async.wait_group %0;" :: "n"(n) : "memory")

#define LDSM_X4(r, addr) \
    asm volatile("ldmatrix.sync.aligned.m8n8.x4.shared.b16 {%0,%1,%2,%3}, [%4];" \
        : "=r"((r)[0]), "=r"((r)[1]), "=r"((r)[2]), "=r"((r)[3]) : "r"(addr))

#define LDSM_X4_T(r, addr) \
    asm volatile("ldmatrix.sync.aligned.m8n8.x4.trans.shared.b16 {%0,%1,%2,%3}, [%4];" \
        : "=r"((r)[0]), "=r"((r)[1]), "=r"((r)[2]), "=r"((r)[3]) : "r"(addr))

#define MMA_BF16(c, a, b0, b1) \
    asm volatile("mma.sync.aligned.m16n8k16.row.col.f32.bf16.bf16.f32 " \
        "{%0,%1,%2,%3}, {%4,%5,%6,%7}, {%8,%9}, {%0,%1,%2,%3};" \
        : "+f"((c)[0]), "+f"((c)[1]), "+f"((c)[2]), "+f"((c)[3]) \
        : "r"((a)[0]), "r"((a)[1]), "r"((a)[2]), "r"((a)[3]), "r"(b0), "r"(b1))

// fast exp2 on the FMA pipe (no MUFU). x clamped to >= -126; |err| < ~1e-7.
__device__ __forceinline__ float fexp2(float x) {
    x = fmaxf(x, -126.0f);
    float t = x + 12582912.0f;
    float r = t - 12582912.0f;
    float f = x - r;
    int e = (__float_as_int(t) + (127 - 0x400000)) << 23;
    float p = 1.5353361883e-4f;
    p = fmaf(p, f, 1.3398874403e-3f);
    p = fmaf(p, f, 9.6184373577e-3f);
    p = fmaf(p, f, 5.5503324712e-2f);
    p = fmaf(p, f, 2.4022647914e-1f);
    p = fmaf(p, f, 6.9314720286e-1f);
    p = fmaf(p, f, 1.0f);
    return p * __int_as_float(e);
}

// ---------------------------------------------------------------------------
// Preprocessing: split fp32 -> (hi, lo) bf16
// ---------------------------------------------------------------------------
__device__ __forceinline__ void bf16_split(float v, __nv_bfloat16& h, __nv_bfloat16& l) {
    h = __float2bfloat16(v);
    l = __float2bfloat16(v - __bfloat162float(h));
}

__device__ __forceinline__ uint32_t pack2bf(float x, float y) {
    __nv_bfloat162 v{__float2bfloat16(x), __float2bfloat16(y)};
    return *(uint32_t*)&v;
}

__global__ __launch_bounds__(256) void split_x_kernel(const float* __restrict__ x) {
    size_t i = (size_t)blockIdx.x * 256 + threadIdx.x;
    float4 v = ((const float4*)x)[i];
    __nv_bfloat16 h0, h1, h2, h3, l0, l1, l2, l3;
    bf16_split(v.x, h0, l0); bf16_split(v.y, h1, l1);
    bf16_split(v.z, h2, l2); bf16_split(v.w, h3, l3);
    __nv_bfloat162* ph = (__nv_bfloat162*)(g_xhi + i * 4);
    __nv_bfloat162* pl = (__nv_bfloat162*)(g_xlo + i * 4);
    ph[0] = __nv_bfloat162{h0, h1}; ph[1] = __nv_bfloat162{h2, h3};
    pl[0] = __nv_bfloat162{l0, l1}; pl[1] = __nv_bfloat162{l2, l3};
}

template <int NN, int WHICH>
__global__ __launch_bounds__(256) void tsplit_w_kernel(const float* __restrict__ W) {
    __shared__ float tile[32][33];
    __nv_bfloat16* Whi = (WHICH == 0) ? g_wahi : g_wphi;
    __nv_bfloat16* Wlo = (WHICH == 0) ? g_walo : g_wplo;
    const int nb = blockIdx.x * 32;
    const int kb = blockIdx.y * 32;
    const int tx = threadIdx.x, ty = threadIdx.y;
#pragma unroll
    for (int r = 0; r < 4; ++r)
        tile[ty + r * 8][tx] = W[(size_t)(kb + ty + r * 8) * NN + nb + tx];
    __syncthreads();
#pragma unroll
    for (int r = 0; r < 4; ++r) {
        const int n = nb + ty + r * 8;
        const int k = kb + tx;
        float v = tile[tx][ty + r * 8];
        __nv_bfloat16 h, l;
        bf16_split(v, h, l);
        Whi[(size_t)n * 1024 + k] = h;
        Wlo[(size_t)n * 1024 + k] = l;
    }
}

// ---------------------------------------------------------------------------
// bf16x3 tensor-core GEMM: C[M,N] = A[M,K] @ Wt[N,K]^T + bias
// CTA tile 128x256 (raised arithmetic intensity: 8 MACs per smem byte).
// K-chunk 32 bf16 (64B rows, xor swizzle). 3-stage cp.async pipeline.
// 8 warps as 2(m) x 4(n); warp tile 64x64 = 4 m-frags x 8 n-frags.
// B fragments consumed immediately per 16-row group (low register liveness).
// SMEM stage (48KB): Ahi@0(8K) Alo@8192 Bhi@16384(16K) Blo@32768(16K).
// ---------------------------------------------------------------------------
template <int Ndim, int MODE>
__global__ __launch_bounds__(256) void hmma_gemm_kernel(
    const float* __restrict__ bias, float* __restrict__ Out)
{
    extern __shared__ __align__(1024) char smem[];
    const uint32_t sbase = smem_to_u32(smem);
    const int tid = threadIdx.x;
    const int lane = tid & 31;
    const int wid = tid >> 5;
    const int wm = wid >> 2;   // 0..1
    const int wn = wid & 3;    // 0..3
    const int m0 = blockIdx.y * 128;
    const int n0 = blockIdx.x * 256;
    constexpr int KT = 32;         // 1024 / 32
    constexpr int STG = 49152;     // stage bytes

    const __nv_bfloat16* Ahi = (MODE == 0) ? g_xhi : g_ahi;
    const __nv_bfloat16* Alo = (MODE == 0) ? g_xlo : g_alo;
    const __nv_bfloat16* Bhi = (MODE == 0) ? g_wahi : g_wphi;
    const __nv_bfloat16* Blo = (MODE == 0) ? g_walo : g_wplo;

    const char* gAh = (const char*)Ahi + (size_t)m0 * 2048;
    const char* gAl = (const char*)Alo + (size_t)m0 * 2048;
    const char* gBh = (const char*)Bhi + (size_t)n0 * 2048;
    const char* gBl = (const char*)Blo + (size_t)n0 * 2048;

    float acc[4][8][4];
#pragma unroll
    for (int mf = 0; mf < 4; ++mf)
#pragma unroll
        for (int nf = 0; nf < 8; ++nf)
#pragma unroll
            for (int e = 0; e < 4; ++e) acc[mf][nf][e] = 0.f;

    auto issue = [&](int c) {
        const uint32_t tb = sbase + (uint32_t)(c % 3) * STG;
        const int kb = c * 64;
        // A planes: 128 rows x 4 chunks = 512 (2/thread)
#pragma unroll
        for (int i = 0; i < 2; ++i) {
            const int idx = tid + i * 256;
            const int row = idx >> 2;
            const int ch = idx & 3;
            const uint32_t soff = row * 64 + ((ch ^ ((row >> 1) & 3)) << 4);
            const size_t goff = (size_t)row * 2048 + ch * 16 + kb;
            cpasync16(tb + 0    + soff, gAh + goff);
            cpasync16(tb + 8192 + soff, gAl + goff);
        }
        // B planes: 256 rows x 4 chunks = 1024 (4/thread)
#pragma unroll
        for (int i = 0; i < 4; ++i) {
            const int idx = tid + i * 256;
            const int row = idx >> 2;
            const int ch = idx & 3;
            const uint32_t soff = row * 64 + ((ch ^ ((row >> 1) & 3)) << 4);
            const size_t goff = (size_t)row * 2048 + ch * 16 + kb;
            cpasync16(tb + 16384 + soff, gBh + goff);
            cpasync16(tb + 32768 + soff, gBl + goff);
        }
        CP_COMMIT();
    };

    issue(0);
    issue(1);

    const int q8 = lane >> 3;
    const int iq = lane & 7;
    const int rowoff_a = ((q8 & 1) << 3) + iq;  // 0..15
    const int khalf = q8 >> 1;                  // 0/1

    for (int c = 0; c < KT; ++c) {
        CP_WAIT(1);
        __syncthreads();
        if (c + 2 < KT) issue(c + 2);

        const uint32_t tb = sbase + (uint32_t)(c % 3) * STG;
        const uint32_t aT = tb, alT = tb + 8192, bT = tb + 16384, blT = tb + 32768;

#pragma unroll
        for (int ks = 0; ks < 2; ++ks) {
            const int cch = ks * 2 + khalf;
            uint32_t ah[4][4], al[4][4];
#pragma unroll
            for (int mf = 0; mf < 4; ++mf) {
                const int row = wm * 64 + mf * 16 + rowoff_a;
                const uint32_t off = row * 64 + ((cch ^ ((row >> 1) & 3)) << 4);
                LDSM_X4(ah[mf], aT + off);
                LDSM_X4(al[mf], alT + off);
            }
#pragma unroll
            for (int np = 0; np < 4; ++np) {
                const int row = wn * 64 + np * 16 + rowoff_a;
                const uint32_t off = row * 64 + ((cch ^ ((row >> 1) & 3)) << 4);
                uint32_t rh[4], rl[4];
                LDSM_X4(rh, bT + off);
                LDSM_X4(rl, blT + off);
                const int nf0 = 2 * np, nf1 = 2 * np + 1;
                // hi*hi
#pragma unroll
                for (int mf = 0; mf < 4; ++mf) {
                    MMA_BF16(acc[mf][nf0], ah[mf], rh[0], rh[2]);
                    MMA_BF16(acc[mf][nf1], ah[mf], rh[1], rh[3]);
                }
                // hi*lo
#pragma unroll
                for (int mf = 0; mf < 4; ++mf) {
                    MMA_BF16(acc[mf][nf0], ah[mf], rl[0], rl[2]);
                    MMA_BF16(acc[mf][nf1], ah[mf], rl[1], rl[3]);
                }
                // lo*hi
#pragma unroll
                for (int mf = 0; mf < 4; ++mf) {
                    MMA_BF16(acc[mf][nf0], al[mf], rh[0], rh[2]);
                    MMA_BF16(acc[mf][nf1], al[mf], rh[1], rh[3]);
                }
            }
        }
    }

    // Epilogue. Frag map: c0,c1 -> (row g, cols 2t,2t+1); c2,c3 -> row g+8.
    const int g = lane >> 2, t = lane & 3;
#pragma unroll
    for (int mf = 0; mf < 4; ++mf) {
        const int r_lo = m0 + wm * 64 + mf * 16 + g;
#pragma unroll
        for (int nf = 0; nf < 8; ++nf) {
            const int col = n0 + wn * 64 + nf * 8 + 2 * t;
            const float b0 = bias[col], b1 = bias[col + 1];
            float v00 = acc[mf][nf][0] + b0, v01 = acc[mf][nf][1] + b1;
            float v10 = acc[mf][nf][2] + b0, v11 = acc[mf][nf][3] + b1;
            if (MODE == 0) {
                const int which = col >> 10;
                const int ci = col & 1023;
                const int hh = ci >> 6;
                const int dd = ci & 63;
                __nv_bfloat16* dh = (which == 0) ? g_qhi : ((which == 1) ? g_khi : g_vhi);
                __nv_bfloat16* dl = (which == 0) ? g_qlo : ((which == 1) ? g_klo : g_vlo);
                __nv_bfloat16 h0, h1, l0, l1;
                const int b_lo = r_lo >> 11, t_lo = r_lo & 2047;
                size_t off = (((size_t)b_lo * HH + hh) * TT + t_lo) * DD + dd;
                bf16_split(v00, h0, l0); bf16_split(v01, h1, l1);
                *(__nv_bfloat162*)(dh + off) = __nv_bfloat162{h0, h1};
                *(__nv_bfloat162*)(dl + off) = __nv_bfloat162{l0, l1};
                const int r_hi = r_lo + 8;
                const int b_hi = r_hi >> 11, t_hi = r_hi & 2047;
                off = (((size_t)b_hi * HH + hh) * TT + t_hi) * DD + dd;
                bf16_split(v10, h0, l0); bf16_split(v11, h1, l1);
                *(__nv_bfloat162*)(dh + off) = __nv_bfloat162{h0, h1};
                *(__nv_bfloat162*)(dl + off) = __nv_bfloat162{l0, l1};
            } else {
                *(float2*)(Out + (size_t)r_lo * Ndim + col) = float2{v00, v01};
                *(float2*)(Out + (size_t)(r_lo + 8) * Ndim + col) = float2{v10, v11};
            }
        }
    }
}

// ---------------------------------------------------------------------------
// Tensor-core flash attention with ALiBi + temperature (unchanged from R8).
// ---------------------------------------------------------------------------
__global__ __launch_bounds__(256) void attn_mma_kernel(const float* __restrict__ temp)
{
    extern __shared__ __align__(1024) char smem[];
    const uint32_t sb = smem_to_u32(smem);
    const int tid = threadIdx.x;
    const int lane = tid & 31;
    const int wid = tid >> 5;
    const int bh = blockIdx.y;
    const int qt = (int)gridDim.x - 1 - blockIdx.x;
    const int b = bh >> 4;
    const int h = bh & 15;

    const float qscale = 0.125f * (1.0f / temp[0]) * 1.44269504088896340736f;
    const float slope = exp2f(-0.5f * (float)(h + 1)) * 1.44269504088896340736f;

    const int q8 = lane >> 3;
    const int iq = lane & 7;
    const int rowoff = ((q8 & 1) << 3) + iq;
    const int khalf = q8 >> 1;
    const int g = lane >> 2, t = lane & 3;

    const char* gQh = (const char*)g_qhi + ((size_t)bh * TT + qt * 128) * 128;
    const char* gQl = (const char*)g_qlo + ((size_t)bh * TT + qt * 128) * 128;
    const char* gKh = (const char*)g_khi + (size_t)bh * TT * 128;
    const char* gKl = (const char*)g_klo + (size_t)bh * TT * 128;
    const char* gVh = (const char*)g_vhi + (size_t)bh * TT * 128;
    const char* gVl = (const char*)g_vlo + (size_t)bh * TT * 128;

    const int nkt = 2 * qt + 2;

#pragma unroll
    for (int i = 0; i < 4; ++i) {
        const int idx = tid + i * 256;
        const int row = idx >> 3;
        const int ch = idx & 7;
        const uint32_t soff = row * 128 + ((ch ^ (row & 7)) << 4);
        const size_t goff = (size_t)row * 128 + ch * 16;
        cpasync16(sb + 0     + soff, gQh + goff);
        cpasync16(sb + 16384 + soff, gQl + goff);
    }
    CP_COMMIT();

    auto issue_kv = [&](int kt) {
        const uint32_t tb = sb + 32768 + (uint32_t)(kt & 1) * 32768;
        const size_t kbase = (size_t)kt * 64 * 128;
#pragma unroll
        for (int i = 0; i < 2; ++i) {
            const int idx = tid + i * 256;
            const int row = idx >> 3;
            const int ch = idx & 7;
            const uint32_t soff = row * 128 + ((ch ^ (row & 7)) << 4);
            const size_t goff = kbase + (size_t)row * 128 + ch * 16;
            cpasync16(tb + 0     + soff, gKh + goff);
            cpasync16(tb + 8192  + soff, gKl + goff);
            cpasync16(tb + 16384 + soff, gVh + goff);
            cpasync16(tb + 24576 + soff, gVl + goff);
        }
        CP_COMMIT();
    };

    issue_kv(0);
    CP_WAIT(1);
    __syncthreads();

    uint32_t qh[4][4], ql[4][4];
#pragma unroll
    for (int ks = 0; ks < 4; ++ks) {
        const int row = wid * 16 + rowoff;
        const int cch = ks * 2 + khalf;
        const uint32_t off = row * 128 + ((cch ^ (row & 7)) << 4);
        LDSM_X4(qh[ks], sb + off);
        LDSM_X4(ql[ks], sb + 16384 + off);
    }

    float oacc[8][4];
#pragma unroll
    for (int nd = 0; nd < 8; ++nd)
#pragma unroll
        for (int e = 0; e < 4; ++e) oacc[nd][e] = 0.f;
    float m0 = -1e30f, m1 = -1e30f, l0 = 0.f, l1 = 0.f;

    const int qrow0 = qt * 128 + wid * 16 + g;
    const int qrow1 = qrow0 + 8;

    for (int kt = 0; kt < nkt; ++kt) {
        if (kt + 1 < nkt) { issue_kv(kt + 1); CP_WAIT(1); }
        else              { CP_WAIT(0); }
        __syncthreads();

        const uint32_t tb = sb + 32768 + (uint32_t)(kt & 1) * 32768;

        float sacc[8][4];
#pragma unroll
        for (int nf = 0; nf < 8; ++nf)
#pragma unroll
            for (int e = 0; e < 4; ++e) sacc[nf][e] = 0.f;

#pragma unroll
        for (int ks = 0; ks < 4; ++ks) {
            const int cch = ks * 2 + khalf;
            uint32_t kbh[8][2], kbl[8][2];
#pragma unroll
            for (int np = 0; np < 4; ++np) {
                const int row = np * 16 + rowoff;
                const uint32_t off = row * 128 + ((cch ^ (row & 7)) << 4);
                uint32_t r[4];
                LDSM_X4(r, tb + off);
                kbh[2 * np][0] = r[0]; kbh[2 * np][1] = r[2];
                kbh[2 * np + 1][0] = r[1]; kbh[2 * np + 1][1] = r[3];
                LDSM_X4(r, tb + 8192 + off);
                kbl[2 * np][0] = r[0]; kbl[2 * np][1] = r[2];
                kbl[2 * np + 1][0] = r[1]; kbl[2 * np + 1][1] = r[3];
            }
#pragma unroll
            for (int nf = 0; nf < 8; ++nf)
                MMA_BF16(sacc[nf], qh[ks], kbh[nf][0], kbh[nf][1]);
#pragma unroll
            for (int nf = 0; nf < 8; ++nf)
                MMA_BF16(sacc[nf], qh[ks], kbl[nf][0], kbl[nf][1]);
#pragma unroll
            for (int nf = 0; nf < 8; ++nf)
                MMA_BF16(sacc[nf], ql[ks], kbh[nf][0], kbh[nf][1]);
        }

        const bool maskt = (kt >= 2 * qt);
        float mx0 = -1e30f, mx1 = -1e30f;
#pragma unroll
        for (int nf = 0; nf < 8; ++nf) {
            const int key = kt * 64 + nf * 8 + 2 * t;
            float s0 = fmaf(sacc[nf][0], qscale, slope * (float)(key - qrow0));
            float s1 = fmaf(sacc[nf][1], qscale, slope * (float)(key + 1 - qrow0));
            float s2 = fmaf(sacc[nf][2], qscale, slope * (float)(key - qrow1));
            float s3 = fmaf(sacc[nf][3], qscale, slope * (float)(key + 1 - qrow1));
            if (maskt) {
                if (key > qrow0) s0 = -1e30f;
                if (key + 1 > qrow0) s1 = -1e30f;
                if (key > qrow1) s2 = -1e30f;
                if (key + 1 > qrow1) s3 = -1e30f;
            }
            sacc[nf][0] = s0; sacc[nf][1] = s1; sacc[nf][2] = s2; sacc[nf][3] = s3;
            mx0 = fmaxf(mx0, fmaxf(s0, s1));
            mx1 = fmaxf(mx1, fmaxf(s2, s3));
        }
        mx0 = fmaxf(mx0, __shfl_xor_sync(0xFFFFFFFFu, mx0, 1));
        mx0 = fmaxf(mx0, __shfl_xor_sync(0xFFFFFFFFu, mx0, 2));
        mx1 = fmaxf(mx1, __shfl_xor_sync(0xFFFFFFFFu, mx1, 1));
        mx1 = fmaxf(mx1, __shfl_xor_sync(0xFFFFFFFFu, mx1, 2));

        const float mn0 = fmaxf(m0, mx0);
        const float mn1 = fmaxf(m1, mx1);
        const float a0 = fexp2(m0 - mn0);
        const float a1 = fexp2(m1 - mn1);
        m0 = mn0; m1 = mn1;
        l0 *= a0; l1 *= a1;
#pragma unroll
        for (int nd = 0; nd < 8; ++nd) {
            oacc[nd][0] *= a0; oacc[nd][1] *= a0;
            oacc[nd][2] *= a1; oacc[nd][3] *= a1;
        }

        float rs0 = 0.f, rs1 = 0.f;
#pragma unroll
        for (int nf = 0; nf < 8; ++nf) {
            float p0 = fexp2(sacc[nf][0] - m0);
            float p1 = fexp2(sacc[nf][1] - m0);
            float p2 = fexp2(sacc[nf][2] - m1);
            float p3 = fexp2(sacc[nf][3] - m1);
            rs0 += p0 + p1; rs1 += p2 + p3;
            sacc[nf][0] = p0; sacc[nf][1] = p1; sacc[nf][2] = p2; sacc[nf][3] = p3;
        }
        rs0 += __shfl_xor_sync(0xFFFFFFFFu, rs0, 1);
        rs0 += __shfl_xor_sync(0xFFFFFFFFu, rs0, 2);
        rs1 += __shfl_xor_sync(0xFFFFFFFFu, rs1, 1);
        rs1 += __shfl_xor_sync(0xFFFFFFFFu, rs1, 2);
        l0 += rs0; l1 += rs1;

        uint32_t pah[4][4], pal[4][4];
#pragma unroll
        for (int jp = 0; jp < 4; ++jp) {
            const int j0 = 2 * jp, j1 = 2 * jp + 1;
            float e[8] = {sacc[j0][0], sacc[j0][1], sacc[j0][2], sacc[j0][3],
                          sacc[j1][0], sacc[j1][1], sacc[j1][2], sacc[j1][3]};
            float eh[8], el[8];
#pragma unroll
            for (int x = 0; x < 8; ++x) {
                __nv_bfloat16 hb = __float2bfloat16(e[x]);
                eh[x] = __bfloat162float(hb);
                el[x] = e[x] - eh[x];
            }
            pah[jp][0] = pack2bf(eh[0], eh[1]); pah[jp][1] = pack2bf(eh[2], eh[3]);
            pah[jp][2] = pack2bf(eh[4], eh[5]); pah[jp][3] = pack2bf(eh[6], eh[7]);
            pal[jp][0] = pack2bf(el[0], el[1]); pal[jp][1] = pack2bf(el[2], el[3]);
            pal[jp][2] = pack2bf(el[4], el[5]); pal[jp][3] = pack2bf(el[6], el[7]);
        }

#pragma unroll
        for (int jp = 0; jp < 4; ++jp) {
            uint32_t vbh[8][2], vbl[8][2];
#pragma unroll
            for (int p = 0; p < 4; ++p) {
                const int row = jp * 16 + rowoff;
                const int cch = 2 * p + khalf;
                const uint32_t off = row * 128 + ((cch ^ (row & 7)) << 4);
                uint32_t r[4];
                LDSM_X4_T(r, tb + 16384 + off);
                vbh[2 * p][0] = r[0]; vbh[2 * p][1] = r[1];
                vbh[2 * p + 1][0] = r[2]; vbh[2 * p + 1][1] = r[3];
                LDSM_X4_T(r, tb + 24576 + off);
                vbl[2 * p][0] = r[0]; vbl[2 * p][1] = r[1];
                vbl[2 * p + 1][0] = r[2]; vbl[2 * p + 1][1] = r[3];
            }
#pragma unroll
            for (int nd = 0; nd < 8; ++nd)
                MMA_BF16(oacc[nd], pah[jp], vbh[nd][0], vbh[nd][1]);
#pragma unroll
            for (int nd = 0; nd < 8; ++nd)
                MMA_BF16(oacc[nd], pal[jp], vbh[nd][0], vbh[nd][1]);
#pragma unroll
            for (int nd = 0; nd < 8; ++nd)
                MMA_BF16(oacc[nd], pah[jp], vbl[nd][0], vbl[nd][1]);
        }
        __syncthreads();
    }

    const float il0 = 1.0f / l0;
    const float il1 = 1.0f / l1;
    const size_t r0off = (size_t)(b * TT + qrow0) * CC + h * 64;
    const size_t r1off = (size_t)(b * TT + qrow1) * CC + h * 64;
#pragma unroll
    for (int nd = 0; nd < 8; ++nd) {
        const int cd = nd * 8 + 2 * t;
        float y0 = oacc[nd][0] * il0, y1 = oacc[nd][1] * il0;
        float y2 = oacc[nd][2] * il1, y3 = oacc[nd][3] * il1;
        __nv_bfloat16 h0, h1, l0b, l1b;
        bf16_split(y0, h0, l0b); bf16_split(y1, h1, l1b);
        *(__nv_bfloat162*)(g_ahi + r0off + cd) = __nv_bfloat162{h0, h1};
        *(__nv_bfloat162*)(g_alo + r0off + cd) = __nv_bfloat162{l0b, l1b};
        bf16_split(y2, h0, l0b); bf16_split(y3, h1, l1b);
        *(__nv_bfloat162*)(g_ahi + r1off + cd) = __nv_bfloat162{h0, h1};
        *(__nv_bfloat162*)(g_alo + r1off + cd) = __nv_bfloat162{l0b, l1b};
    }
}

// ---------------------------------------------------------------------------
// Harness entry
// ---------------------------------------------------------------------------
extern "C" void kernel_launch(void* const* d_in, const int* in_sizes, int n_in,
                              void* d_out, int out_size)
{
    const float* x      = (const float*)d_in[0];
    const float* W_attn = (const float*)d_in[1];
    const float* b_attn = (const float*)d_in[2];
    const float* W_proj = (const float*)d_in[3];
    const float* b_proj = (const float*)d_in[4];
    const float* temp   = (const float*)d_in[5];
    float* out = (float*)d_out;

    const int GEMM_SMEM = 3 * 49152;   // 147456
    const int ATTN_SMEM = 3 * 32768;   // 98304
    cudaFuncSetAttribute(hmma_gemm_kernel<3 * CC, 0>,
                         cudaFuncAttributeMaxDynamicSharedMemorySize, GEMM_SMEM);
    cudaFuncSetAttribute(hmma_gemm_kernel<CC, 1>,
                         cudaFuncAttributeMaxDynamicSharedMemorySize, GEMM_SMEM);
    cudaFuncSetAttribute(attn_mma_kernel,
                         cudaFuncAttributeMaxDynamicSharedMemorySize, ATTN_SMEM);

    // 0) precision-split inputs (bf16 hi/lo) + weight transposes
    split_x_kernel<<<(MM * CC / 4) / 256, 256>>>(x);
    tsplit_w_kernel<3 * CC, 0><<<dim3(3 * CC / 32, CC / 32), dim3(32, 8)>>>(W_attn);
    tsplit_w_kernel<CC, 1><<<dim3(CC / 32, CC / 32), dim3(32, 8)>>>(W_proj);

    // 1) QKV = x @ W_attn + b_attn  (bf16x3 HMMA, 128x256 tiles)
    hmma_gemm_kernel<3 * CC, 0><<<dim3(3 * CC / 256, MM / 128), 256, GEMM_SMEM>>>(
        b_attn, nullptr);

    // 2) tensor-core causal ALiBi attention -> bf16-split A for proj
    attn_mma_kernel<<<dim3(TT / 128, BB * HH), 256, ATTN_SMEM>>>(temp);

    // 3) out = att @ W_proj + b_proj  (bf16x3 HMMA, 128x256 tiles)
    hmma_gemm_kernel<CC, 1><<<dim3(CC / 256, MM / 128), 256, GEMM_SMEM>>>(
        b_proj, out);
}